// round 2
// baseline (speedup 1.0000x reference)
#include <cuda_runtime.h>
#include <math.h>

#define EMBED 1024
#define HEADS 16
#define HDIM  64
#define BATCH 2
#define SEQ   2048
#define MROWS (BATCH*SEQ)   // 4096

// ---------------- device scratch (alloc-free rule: __device__ globals) ------
__device__ float g_Q[(size_t)BATCH*HEADS*SEQ*HDIM];   // 16 MB, [B,H,S,Dh]
__device__ float g_K[(size_t)BATCH*HEADS*SEQ*HDIM];
__device__ float g_V[(size_t)BATCH*HEADS*SEQ*HDIM];
__device__ float g_A[(size_t)MROWS*EMBED];            // attention out, [B,S,E]

// ---------------- tf32 helpers ---------------------------------------------
__device__ __forceinline__ unsigned f2tf(float x) {
    unsigned r;
    asm("cvt.rna.tf32.f32 %0, %1;" : "=r"(r) : "f"(x));
    return r;
}

__device__ __forceinline__ void mma8(float* c, const unsigned* a, const unsigned* b) {
    asm volatile(
        "mma.sync.aligned.m16n8k8.row.col.f32.tf32.tf32.f32 "
        "{%0,%1,%2,%3}, {%4,%5,%6,%7}, {%8,%9}, {%0,%1,%2,%3};\n"
        : "+f"(c[0]), "+f"(c[1]), "+f"(c[2]), "+f"(c[3])
        : "r"(a[0]), "r"(a[1]), "r"(a[2]), "r"(a[3]), "r"(b[0]), "r"(b[1]));
}

// ---------------- GEMM: C[4096x1024] = A[4096x1024] * W[1024x1024] + bias ---
// mode 0/1/2: A = Aext (x), C = g_Q/g_K/g_V with split-head output layout
// mode 3    : A = g_A,      C = Cext (d_out), plain row-major layout
#define GP_AS 36
#define GP_BS 136

__global__ __launch_bounds__(256, 1)
void gemm_tf32(const float* __restrict__ Aext, const float* __restrict__ W,
               const float* __restrict__ bias, float* __restrict__ Cext, int mode)
{
    __shared__ float As[128 * GP_AS];
    __shared__ float Bs[32 * GP_BS];

    const float* A;
    float* C;
    int split;
    if (mode == 3) { A = g_A;  C = Cext; split = 0; }
    else {
        A = Aext; split = 1;
        C = (mode == 0) ? g_Q : (mode == 1) ? g_K : g_V;
    }

    int m0 = blockIdx.x * 128;
    int n0 = blockIdx.y * 128;
    int tid = threadIdx.x;
    int wid = tid >> 5, lane = tid & 31;
    int gid = lane >> 2, tig = lane & 3;
    int wrow = wid >> 2, wcol = wid & 3;   // 2x4 warp grid -> each warp 64x32

    float c[4][4][4];
#pragma unroll
    for (int i = 0; i < 4; i++)
#pragma unroll
        for (int j = 0; j < 4; j++)
#pragma unroll
            for (int k = 0; k < 4; k++) c[i][j][k] = 0.f;

    for (int kt = 0; kt < EMBED; kt += 32) {
        // A tile 128x32
#pragma unroll
        for (int i = 0; i < 4; i++) {
            int lin = tid + i * 256;
            int r = lin >> 3, c4 = lin & 7;
            float4 v = *(const float4*)(A + (size_t)(m0 + r) * EMBED + kt + c4 * 4);
            *(float4*)(As + r * GP_AS + c4 * 4) = v;
        }
        // B tile 32x128
#pragma unroll
        for (int i = 0; i < 4; i++) {
            int lin = tid + i * 256;
            int r = lin >> 5, c4 = lin & 31;
            float4 v = *(const float4*)(W + (size_t)(kt + r) * EMBED + n0 + c4 * 4);
            *(float4*)(Bs + r * GP_BS + c4 * 4) = v;
        }
        __syncthreads();

#pragma unroll
        for (int kk = 0; kk < 32; kk += 8) {
            unsigned af[4][4], bf[4][2];
#pragma unroll
            for (int mf = 0; mf < 4; mf++) {
                const float* p = As + (wrow * 64 + mf * 16 + gid) * GP_AS + kk + tig;
                af[mf][0] = f2tf(p[0]);
                af[mf][1] = f2tf(p[8 * GP_AS]);
                af[mf][2] = f2tf(p[4]);
                af[mf][3] = f2tf(p[8 * GP_AS + 4]);
            }
#pragma unroll
            for (int nf = 0; nf < 4; nf++) {
                const float* p = Bs + (kk + tig) * GP_BS + wcol * 32 + nf * 8 + gid;
                bf[nf][0] = f2tf(p[0]);
                bf[nf][1] = f2tf(p[4 * GP_BS]);
            }
#pragma unroll
            for (int mf = 0; mf < 4; mf++)
#pragma unroll
                for (int nf = 0; nf < 4; nf++)
                    mma8(c[mf][nf], af[mf], bf[nf]);
        }
        __syncthreads();
    }

    // epilogue: bias + (optional) split-head remap, float2 stores
#pragma unroll
    for (int mf = 0; mf < 4; mf++) {
#pragma unroll
        for (int nf = 0; nf < 4; nf++) {
            int rbase = m0 + wrow * 64 + mf * 16 + gid;
            int n = n0 + wcol * 32 + nf * 8 + tig * 2;
            float b0v = bias[n], b1v = bias[n + 1];
#pragma unroll
            for (int half = 0; half < 2; half++) {
                int r = rbase + half * 8;
                float v0 = c[mf][nf][half * 2 + 0] + b0v;
                float v1 = c[mf][nf][half * 2 + 1] + b1v;
                size_t oidx;
                if (split) {
                    int b = r >> 11, s = r & 2047;
                    int h = n >> 6, d = n & 63;
                    oidx = (((size_t)(b * HEADS + h)) * SEQ + s) * HDIM + d;
                } else {
                    oidx = (size_t)r * EMBED + n;
                }
                *(float2*)(C + oidx) = make_float2(v0, v1);
            }
        }
    }
}

// ---------------- fused flash attention ------------------------------------
// grid: (16 q-blocks, 32 b*h). CTA: 256 threads. Q block of 128 rows resident.
#define QS_LD 72
#define SS_LD 132
#define ATT_SMEM_FLOATS (128*QS_LD*2 + 128*SS_LD + 3*128)

__global__ __launch_bounds__(256, 1)
void attn_kernel()
{
    extern __shared__ float sm[];
    float* Qs   = sm;                     // [128][72]
    float* Ks   = Qs + 128 * QS_LD;       // [128][72]  (K tile, reused for V)
    float* Ss   = Ks + 128 * QS_LD;       // [128][132] (scores -> P)
    float* sm_m = Ss + 128 * SS_LD;       // [128]
    float* sm_l = sm_m + 128;             // [128]
    float* sm_a = sm_l + 128;             // [128]

    int qb = blockIdx.x;
    int bh = blockIdx.y;
    int tid = threadIdx.x;
    int wid = tid >> 5, lane = tid & 31;
    int gid = lane >> 2, tig = lane & 3;
    int wrow = wid >> 2, wcol = wid & 3;

    const float* Qg = g_Q + (size_t)bh * SEQ * HDIM + (size_t)qb * 128 * HDIM;
    const float* Kg = g_K + (size_t)bh * SEQ * HDIM;
    const float* Vg = g_V + (size_t)bh * SEQ * HDIM;

    // load Q block 128x64
#pragma unroll
    for (int i = 0; i < 8; i++) {
        int lin = tid + i * 256;
        int r = lin >> 4, c4 = lin & 15;
        float4 v = *(const float4*)(Qg + (size_t)r * HDIM + c4 * 4);
        *(float4*)(Qs + r * QS_LD + c4 * 4) = v;
    }
    if (tid < 128) { sm_m[tid] = -1e30f; sm_l[tid] = 0.f; }

    // O accumulators: warp wid owns rows [16*wid, 16*wid+16), 8 n-frags x 8 cols
    float o[8][4];
#pragma unroll
    for (int i = 0; i < 8; i++)
#pragma unroll
        for (int j = 0; j < 4; j++) o[i][j] = 0.f;

    for (int j = 0; j < SEQ / 128; j++) {
        __syncthreads();   // protect Ks (prev PV) / Ss (prev PV reads)
        // load K tile 128x64
#pragma unroll
        for (int i = 0; i < 8; i++) {
            int lin = tid + i * 256;
            int r = lin >> 4, c4 = lin & 15;
            float4 v = *(const float4*)(Kg + (size_t)(j * 128 + r) * HDIM + c4 * 4);
            *(float4*)(Ks + r * QS_LD + c4 * 4) = v;
        }
        __syncthreads();

        // S = Q K^T * (1/8); warps tile 128x128 as 2x4 (64x32 each)
        {
            float s[4][4][4];
#pragma unroll
            for (int a = 0; a < 4; a++)
#pragma unroll
                for (int b = 0; b < 4; b++)
#pragma unroll
                    for (int k = 0; k < 4; k++) s[a][b][k] = 0.f;

#pragma unroll
            for (int kk = 0; kk < 64; kk += 8) {
                unsigned af[4][4], bf[4][2];
#pragma unroll
                for (int mf = 0; mf < 4; mf++) {
                    const float* p = Qs + (wrow * 64 + mf * 16 + gid) * QS_LD + kk + tig;
                    af[mf][0] = f2tf(p[0]);
                    af[mf][1] = f2tf(p[8 * QS_LD]);
                    af[mf][2] = f2tf(p[4]);
                    af[mf][3] = f2tf(p[8 * QS_LD + 4]);
                }
#pragma unroll
                for (int nf = 0; nf < 4; nf++) {
                    const float* p = Ks + (wcol * 32 + nf * 8 + gid) * QS_LD + kk + tig;
                    bf[nf][0] = f2tf(p[0]);
                    bf[nf][1] = f2tf(p[4]);
                }
#pragma unroll
                for (int mf = 0; mf < 4; mf++)
#pragma unroll
                    for (int nf = 0; nf < 4; nf++)
                        mma8(s[mf][nf], af[mf], bf[nf]);
            }
            const float sc = 0.125f;  // 1/sqrt(64)
#pragma unroll
            for (int mf = 0; mf < 4; mf++)
#pragma unroll
                for (int nf = 0; nf < 4; nf++) {
                    int r = wrow * 64 + mf * 16 + gid;
                    int cc = wcol * 32 + nf * 8 + tig * 2;
                    Ss[r * SS_LD + cc]           = s[mf][nf][0] * sc;
                    Ss[r * SS_LD + cc + 1]       = s[mf][nf][1] * sc;
                    Ss[(r + 8) * SS_LD + cc]     = s[mf][nf][2] * sc;
                    Ss[(r + 8) * SS_LD + cc + 1] = s[mf][nf][3] * sc;
                }
        }
        __syncthreads();

        // load V tile into Ks (K reads are done) while doing the softmax
#pragma unroll
        for (int i = 0; i < 8; i++) {
            int lin = tid + i * 256;
            int r = lin >> 4, c4 = lin & 15;
            float4 v = *(const float4*)(Vg + (size_t)(j * 128 + r) * HDIM + c4 * 4);
            *(float4*)(Ks + r * QS_LD + c4 * 4) = v;
        }
        // online softmax: 2 threads per row, 64 cols each
        {
            int row = tid >> 1, half = tid & 1;
            float* srow = Ss + row * SS_LD + half * 64;
            float mx = -1e30f;
#pragma unroll
            for (int cidx = 0; cidx < 64; cidx++) mx = fmaxf(mx, srow[cidx]);
            mx = fmaxf(mx, __shfl_xor_sync(0xffffffffu, mx, 1));
            float m_old = sm_m[row];
            float m_new = fmaxf(m_old, mx);
            float sumv = 0.f;
#pragma unroll
            for (int cidx = 0; cidx < 64; cidx++) {
                float p = __expf(srow[cidx] - m_new);
                srow[cidx] = p;
                sumv += p;
            }
            sumv += __shfl_xor_sync(0xffffffffu, sumv, 1);
            if (half == 0) {
                float alpha = __expf(m_old - m_new);
                sm_a[row] = alpha;
                sm_m[row] = m_new;
                sm_l[row] = sm_l[row] * alpha + sumv;
            }
        }
        __syncthreads();

        // rescale O, then O += P * V ; warp wid -> rows [16*wid, 16*wid+16)
        {
            float a_lo = sm_a[wid * 16 + gid];
            float a_hi = sm_a[wid * 16 + gid + 8];
#pragma unroll
            for (int nf = 0; nf < 8; nf++) {
                o[nf][0] *= a_lo; o[nf][1] *= a_lo;
                o[nf][2] *= a_hi; o[nf][3] *= a_hi;
            }
#pragma unroll
            for (int kk = 0; kk < 128; kk += 8) {
                unsigned af[4];
                const float* p = Ss + (wid * 16 + gid) * SS_LD + kk + tig;
                af[0] = f2tf(p[0]);
                af[1] = f2tf(p[8 * SS_LD]);
                af[2] = f2tf(p[4]);
                af[3] = f2tf(p[8 * SS_LD + 4]);
#pragma unroll
                for (int nf = 0; nf < 8; nf++) {
                    unsigned bf[2];
                    const float* pb = Ks + (kk + tig) * QS_LD + nf * 8 + gid;
                    bf[0] = f2tf(pb[0]);
                    bf[1] = f2tf(pb[4 * QS_LD]);
                    mma8(o[nf], af, bf);
                }
            }
        }
    }

    // epilogue: O /= l ; write to g_A in [B,S,E] layout (undo head split)
    {
        int b = bh >> 4, h = bh & 15;
        float linv_lo = 1.f / sm_l[wid * 16 + gid];
        float linv_hi = 1.f / sm_l[wid * 16 + gid + 8];
        size_t row_lo = (size_t)(b * SEQ + qb * 128 + wid * 16 + gid);
#pragma unroll
        for (int nf = 0; nf < 8; nf++) {
            int d = nf * 8 + tig * 2;
            size_t base = row_lo * EMBED + (size_t)h * HDIM + d;
            *(float2*)(g_A + base)             = make_float2(o[nf][0] * linv_lo, o[nf][1] * linv_lo);
            *(float2*)(g_A + base + 8 * EMBED) = make_float2(o[nf][2] * linv_hi, o[nf][3] * linv_hi);
        }
    }
}

// ---------------- launch ----------------------------------------------------
extern "C" void kernel_launch(void* const* d_in, const int* in_sizes, int n_in,
                              void* d_out, int out_size)
{
    const float* x  = (const float*)d_in[0];
    const float* Wq = (const float*)d_in[1];
    const float* bq = (const float*)d_in[2];
    const float* Wk = (const float*)d_in[3];
    const float* bk = (const float*)d_in[4];
    const float* Wv = (const float*)d_in[5];
    const float* bv = (const float*)d_in[6];
    const float* Wo = (const float*)d_in[7];
    const float* bo = (const float*)d_in[8];
    float* out = (float*)d_out;

    dim3 gg(MROWS / 128, EMBED / 128);  // 32 x 8

    gemm_tf32<<<gg, 256>>>(x, Wq, bq, nullptr, 0);
    gemm_tf32<<<gg, 256>>>(x, Wk, bk, nullptr, 1);
    gemm_tf32<<<gg, 256>>>(x, Wv, bv, nullptr, 2);

    int smem_bytes = ATT_SMEM_FLOATS * (int)sizeof(float);
    cudaFuncSetAttribute(attn_kernel, cudaFuncAttributeMaxDynamicSharedMemorySize, smem_bytes);
    attn_kernel<<<dim3(SEQ / 128, BATCH * HEADS), 256, smem_bytes>>>();

    gemm_tf32<<<gg, 256>>>(nullptr, Wo, bo, out, 3);
}

// round 3
// speedup vs baseline: 1.4902x; 1.4902x over previous
#include <cuda_runtime.h>
#include <math.h>

#define EMBED 1024
#define HEADS 16
#define HDIM  64
#define BATCH 2
#define SEQ   2048
#define MROWS (BATCH*SEQ)   // 4096

// ---------------- device scratch (alloc-free rule: __device__ globals) ------
__device__ float g_Q[(size_t)BATCH*HEADS*SEQ*HDIM];   // [B,H,S,Dh]
__device__ float g_K[(size_t)BATCH*HEADS*SEQ*HDIM];
__device__ float g_V[(size_t)BATCH*HEADS*SEQ*HDIM];
__device__ float g_A[(size_t)MROWS*EMBED];            // attention out, [B,S,E]

// ---------------- helpers ----------------------------------------------------
__device__ __forceinline__ unsigned f2tf(float x) {
    unsigned r;
    asm("cvt.rna.tf32.f32 %0, %1;" : "=r"(r) : "f"(x));
    return r;
}

__device__ __forceinline__ float ex2f(float x) {
    float y;
    asm("ex2.approx.ftz.f32 %0, %1;" : "=f"(y) : "f"(x));
    return y;
}

__device__ __forceinline__ void mma8(float* c, const unsigned* a, const unsigned* b) {
    asm volatile(
        "mma.sync.aligned.m16n8k8.row.col.f32.tf32.tf32.f32 "
        "{%0,%1,%2,%3}, {%4,%5,%6,%7}, {%8,%9}, {%0,%1,%2,%3};\n"
        : "+f"(c[0]), "+f"(c[1]), "+f"(c[2]), "+f"(c[3])
        : "r"(a[0]), "r"(a[1]), "r"(a[2]), "r"(a[3]), "r"(b[0]), "r"(b[1]));
}

__device__ __forceinline__ void cpa16(float* dst, const float* src) {
    unsigned d = (unsigned)__cvta_generic_to_shared(dst);
    asm volatile("cp.async.cg.shared.global [%0], [%1], 16;\n" :: "r"(d), "l"(src));
}

// ---------------- GEMM: C[4096x1024] = A[4096x1024] * W[1024x1024] + bias ---
// split=1: A=x, grid.z selects (Wq->g_Q | Wk->g_K | Wv->g_V), split-head layout
// split=0: A=g_A, C=Cext (d_out), row-major
#define GS_A 36
#define GS_B 136
#define G_STG (128*GS_A + 32*GS_B)          // floats per stage: 8960
#define GEMM_SMEM_BYTES (2*G_STG*4)         // 71680

__global__ __launch_bounds__(256, 1)
void gemm_tf32(const float* __restrict__ Aext,
               const float* __restrict__ W0, const float* __restrict__ W1,
               const float* __restrict__ W2,
               const float* __restrict__ B0, const float* __restrict__ B1,
               const float* __restrict__ B2,
               float* __restrict__ Cext, int split)
{
    extern __shared__ float sm[];

    const float* A;
    const float* W;
    const float* bias;
    float* C;
    if (split) {
        A = Aext;
        int z = blockIdx.z;
        W    = (z == 0) ? W0 : (z == 1) ? W1 : W2;
        bias = (z == 0) ? B0 : (z == 1) ? B1 : B2;
        C    = (z == 0) ? g_Q : (z == 1) ? g_K : g_V;
    } else {
        A = g_A; W = W0; bias = B0; C = Cext;
    }

    int m0 = blockIdx.x * 128;
    int n0 = blockIdx.y * 128;
    int tid = threadIdx.x;
    int wid = tid >> 5, lane = tid & 31;
    int gid = lane >> 2, tig = lane & 3;
    int wrow = wid >> 2, wcol = wid & 3;

    float c[4][4][4];
#pragma unroll
    for (int i = 0; i < 4; i++)
#pragma unroll
        for (int j = 0; j < 4; j++)
#pragma unroll
            for (int k = 0; k < 4; k++) c[i][j][k] = 0.f;

    auto issue = [&](int kt, int s) {
        float* As = sm + s * G_STG;
        float* Bs = As + 128 * GS_A;
#pragma unroll
        for (int i = 0; i < 4; i++) {
            int lin = tid + i * 256;
            int r = lin >> 3, c4 = lin & 7;
            cpa16(As + r * GS_A + c4 * 4, A + (size_t)(m0 + r) * EMBED + kt + c4 * 4);
        }
#pragma unroll
        for (int i = 0; i < 4; i++) {
            int lin = tid + i * 256;
            int r = lin >> 5, c4 = lin & 31;
            cpa16(Bs + r * GS_B + c4 * 4, W + (size_t)(kt + r) * EMBED + n0 + c4 * 4);
        }
        asm volatile("cp.async.commit_group;");
    };

    issue(0, 0);

    for (int it = 0; it < EMBED / 32; ++it) {
        int s = it & 1;
        if (it + 1 < EMBED / 32) {
            issue((it + 1) * 32, s ^ 1);
            asm volatile("cp.async.wait_group 1;");
        } else {
            asm volatile("cp.async.wait_group 0;");
        }
        __syncthreads();

        const float* As = sm + s * G_STG;
        const float* Bs = As + 128 * GS_A;

#pragma unroll
        for (int kk = 0; kk < 32; kk += 8) {
            unsigned af[4][4], bf[4][2];
#pragma unroll
            for (int mf = 0; mf < 4; mf++) {
                const float* p = As + (wrow * 64 + mf * 16 + gid) * GS_A + kk + tig;
                af[mf][0] = f2tf(p[0]);
                af[mf][1] = f2tf(p[8 * GS_A]);
                af[mf][2] = f2tf(p[4]);
                af[mf][3] = f2tf(p[8 * GS_A + 4]);
            }
#pragma unroll
            for (int nf = 0; nf < 4; nf++) {
                const float* p = Bs + (kk + tig) * GS_B + wcol * 32 + nf * 8 + gid;
                bf[nf][0] = f2tf(p[0]);
                bf[nf][1] = f2tf(p[4 * GS_B]);
            }
#pragma unroll
            for (int mf = 0; mf < 4; mf++)
#pragma unroll
                for (int nf = 0; nf < 4; nf++)
                    mma8(c[mf][nf], af[mf], bf[nf]);
        }
        __syncthreads();
    }

    // epilogue: bias + (optional) split-head remap
#pragma unroll
    for (int mf = 0; mf < 4; mf++) {
#pragma unroll
        for (int nf = 0; nf < 4; nf++) {
            int rbase = m0 + wrow * 64 + mf * 16 + gid;
            int n = n0 + wcol * 32 + nf * 8 + tig * 2;
            float b0v = bias[n], b1v = bias[n + 1];
#pragma unroll
            for (int half = 0; half < 2; half++) {
                int r = rbase + half * 8;
                float v0 = c[mf][nf][half * 2 + 0] + b0v;
                float v1 = c[mf][nf][half * 2 + 1] + b1v;
                size_t oidx;
                if (split) {
                    int b = r >> 11, s2 = r & 2047;
                    int h = n >> 6, d = n & 63;
                    oidx = (((size_t)(b * HEADS + h)) * SEQ + s2) * HDIM + d;
                } else {
                    oidx = (size_t)r * EMBED + n;
                }
                *(float2*)(C + oidx) = make_float2(v0, v1);
            }
        }
    }
}

// ---------------- fused flash attention (register softmax) ------------------
// grid (16 qb, 32 bh), 256 threads. Warp w owns query rows [16w,16w+16).
// Q in registers, S/P in registers, K/V double-buffered via cp.async.
#define KS_LD 68     // bank-conflict-free for (row=n+gid, col=k+tig) reads
#define VS_LD 72     // bank-conflict-free for (row=k+tig, col=n+gid) reads
#define ATT_SMEM_BYTES ((2*128*KS_LD + 2*128*VS_LD)*4)   // 143360

__global__ __launch_bounds__(256, 1)
void attn_kernel()
{
    extern __shared__ float sm[];
    float* K0 = sm;
    float* K1 = K0 + 128 * KS_LD;
    float* V0 = K1 + 128 * KS_LD;
    float* V1 = V0 + 128 * VS_LD;

    int qb = blockIdx.x;
    int bh = blockIdx.y;
    int tid = threadIdx.x;
    int wid = tid >> 5, lane = tid & 31;
    int gid = lane >> 2, tig = lane & 3;

    const float* Qg = g_Q + (size_t)bh * SEQ * HDIM + (size_t)qb * 128 * HDIM;
    const float* Kg = g_K + (size_t)bh * SEQ * HDIM;
    const float* Vg = g_V + (size_t)bh * SEQ * HDIM;

    // ---- stage Q through K0, extract per-warp Q fragments into registers ----
#pragma unroll
    for (int i = 0; i < 8; i++) {
        int lin = tid + i * 256;
        int r = lin >> 4, c4 = lin & 15;
        *(float4*)(K0 + r * KS_LD + c4 * 4) = *(const float4*)(Qg + (size_t)r * HDIM + c4 * 4);
    }
    __syncthreads();
    unsigned qf[8][4];
    {
        const float* p0 = K0 + (wid * 16 + gid) * KS_LD;
#pragma unroll
        for (int kc = 0; kc < 8; kc++) {
            const float* p = p0 + kc * 8 + tig;
            qf[kc][0] = f2tf(p[0]);
            qf[kc][1] = f2tf(p[8 * KS_LD]);
            qf[kc][2] = f2tf(p[4]);
            qf[kc][3] = f2tf(p[8 * KS_LD + 4]);
        }
    }
    __syncthreads();

    float o[8][4];
#pragma unroll
    for (int i = 0; i < 8; i++)
#pragma unroll
        for (int j = 0; j < 4; j++) o[i][j] = 0.f;

    float m0 = -1e30f, m1 = -1e30f, l0 = 0.f, l1 = 0.f;
    const float CC = 0.125f * 1.44269504f;   // (1/sqrt(64)) * log2(e)

    auto issueKV = [&](int j, int s) {
        float* Kd = s ? K1 : K0;
        float* Vd = s ? V1 : V0;
        const float* Ksrc = Kg + (size_t)j * 128 * HDIM;
        const float* Vsrc = Vg + (size_t)j * 128 * HDIM;
#pragma unroll
        for (int i = 0; i < 8; i++) {
            int lin = tid + i * 256;
            int r = lin >> 4, c4 = lin & 15;
            cpa16(Kd + r * KS_LD + c4 * 4, Ksrc + (size_t)r * HDIM + c4 * 4);
        }
#pragma unroll
        for (int i = 0; i < 8; i++) {
            int lin = tid + i * 256;
            int r = lin >> 4, c4 = lin & 15;
            cpa16(Vd + r * VS_LD + c4 * 4, Vsrc + (size_t)r * HDIM + c4 * 4);
        }
        asm volatile("cp.async.commit_group;");
    };

    issueKV(0, 0);

    const int srcA = (lane & 28) | (tig >> 1);
    const int srcB = srcA + 2;
    const bool odd = (tig & 1);

    for (int j = 0; j < SEQ / 128; j++) {
        int s = j & 1;
        if (j + 1 < SEQ / 128) {
            issueKV(j + 1, s ^ 1);
            asm volatile("cp.async.wait_group 1;");
        } else {
            asm volatile("cp.async.wait_group 0;");
        }
        __syncthreads();

        const float* Kb = s ? K1 : K0;
        const float* Vb = s ? V1 : V0;

        // ---- S = Q K^T (warp owns 16 rows x 128 cols; S in registers) ----
        float sv[16][4];
#pragma unroll
        for (int nf = 0; nf < 16; nf++)
#pragma unroll
            for (int k = 0; k < 4; k++) sv[nf][k] = 0.f;

#pragma unroll
        for (int kc = 0; kc < 8; kc++) {
#pragma unroll
            for (int nf = 0; nf < 16; nf++) {
                const float* pb = Kb + (nf * 8 + gid) * KS_LD + kc * 8 + tig;
                unsigned bf[2] = { f2tf(pb[0]), f2tf(pb[4]) };
                mma8(sv[nf], qf[kc], bf);
            }
        }

        // ---- online softmax, fully in registers (rows gid / gid+8) ----
        float mx0 = -1e30f, mx1 = -1e30f;
#pragma unroll
        for (int nf = 0; nf < 16; nf++) {
            mx0 = fmaxf(mx0, fmaxf(sv[nf][0], sv[nf][1]));
            mx1 = fmaxf(mx1, fmaxf(sv[nf][2], sv[nf][3]));
        }
        mx0 = fmaxf(mx0, __shfl_xor_sync(0xffffffffu, mx0, 1));
        mx0 = fmaxf(mx0, __shfl_xor_sync(0xffffffffu, mx0, 2));
        mx1 = fmaxf(mx1, __shfl_xor_sync(0xffffffffu, mx1, 1));
        mx1 = fmaxf(mx1, __shfl_xor_sync(0xffffffffu, mx1, 2));

        float mn0 = fmaxf(m0, mx0 * CC);
        float mn1 = fmaxf(m1, mx1 * CC);
        float al0 = ex2f(m0 - mn0);
        float al1 = ex2f(m1 - mn1);

        float s0 = 0.f, s1 = 0.f;
#pragma unroll
        for (int nf = 0; nf < 16; nf++) {
            float p;
            p = ex2f(fmaf(sv[nf][0], CC, -mn0)); sv[nf][0] = p; s0 += p;
            p = ex2f(fmaf(sv[nf][1], CC, -mn0)); sv[nf][1] = p; s0 += p;
            p = ex2f(fmaf(sv[nf][2], CC, -mn1)); sv[nf][2] = p; s1 += p;
            p = ex2f(fmaf(sv[nf][3], CC, -mn1)); sv[nf][3] = p; s1 += p;
        }
        s0 += __shfl_xor_sync(0xffffffffu, s0, 1);
        s0 += __shfl_xor_sync(0xffffffffu, s0, 2);
        s1 += __shfl_xor_sync(0xffffffffu, s1, 1);
        s1 += __shfl_xor_sync(0xffffffffu, s1, 2);

        l0 = l0 * al0 + s0;
        l1 = l1 * al1 + s1;
        m0 = mn0; m1 = mn1;

#pragma unroll
        for (int vf = 0; vf < 8; vf++) {
            o[vf][0] *= al0; o[vf][1] *= al0;
            o[vf][2] *= al1; o[vf][3] *= al1;
        }

        // ---- O += P V : shuffle C-layout P into A-layout fragments ----
#pragma unroll
        for (int kc = 0; kc < 16; kc++) {
            unsigned p0 = f2tf(sv[kc][0]), p1 = f2tf(sv[kc][1]);
            unsigned p2 = f2tf(sv[kc][2]), p3 = f2tf(sv[kc][3]);
            unsigned tA0 = __shfl_sync(0xffffffffu, p0, srcA);
            unsigned tA1 = __shfl_sync(0xffffffffu, p1, srcA);
            unsigned tA2 = __shfl_sync(0xffffffffu, p2, srcA);
            unsigned tA3 = __shfl_sync(0xffffffffu, p3, srcA);
            unsigned tB0 = __shfl_sync(0xffffffffu, p0, srcB);
            unsigned tB1 = __shfl_sync(0xffffffffu, p1, srcB);
            unsigned tB2 = __shfl_sync(0xffffffffu, p2, srcB);
            unsigned tB3 = __shfl_sync(0xffffffffu, p3, srcB);
            unsigned a[4];
            a[0] = odd ? tA1 : tA0;
            a[1] = odd ? tA3 : tA2;
            a[2] = odd ? tB1 : tB0;
            a[3] = odd ? tB3 : tB2;
#pragma unroll
            for (int vf = 0; vf < 8; vf++) {
                const float* pb = Vb + (kc * 8 + tig) * VS_LD + vf * 8 + gid;
                unsigned bf[2] = { f2tf(pb[0]), f2tf(pb[4 * VS_LD]) };
                mma8(o[vf], a, bf);
            }
        }
        __syncthreads();
    }

    // ---- epilogue: O/l, write to g_A in [B,S,E] layout ----
    {
        int b = bh >> 4, h = bh & 15;
        float li0 = 1.f / l0;
        float li1 = 1.f / l1;
        size_t row = (size_t)(b * SEQ + qb * 128 + wid * 16 + gid);
#pragma unroll
        for (int vf = 0; vf < 8; vf++) {
            int d = vf * 8 + tig * 2;
            size_t base = row * EMBED + (size_t)h * HDIM + d;
            *(float2*)(g_A + base)             = make_float2(o[vf][0] * li0, o[vf][1] * li0);
            *(float2*)(g_A + base + 8 * EMBED) = make_float2(o[vf][2] * li1, o[vf][3] * li1);
        }
    }
}

// ---------------- launch ----------------------------------------------------
extern "C" void kernel_launch(void* const* d_in, const int* in_sizes, int n_in,
                              void* d_out, int out_size)
{
    const float* x  = (const float*)d_in[0];
    const float* Wq = (const float*)d_in[1];
    const float* bq = (const float*)d_in[2];
    const float* Wk = (const float*)d_in[3];
    const float* bk = (const float*)d_in[4];
    const float* Wv = (const float*)d_in[5];
    const float* bv = (const float*)d_in[6];
    const float* Wo = (const float*)d_in[7];
    const float* bo = (const float*)d_in[8];
    float* out = (float*)d_out;

    cudaFuncSetAttribute(gemm_tf32, cudaFuncAttributeMaxDynamicSharedMemorySize,
                         GEMM_SMEM_BYTES);
    cudaFuncSetAttribute(attn_kernel, cudaFuncAttributeMaxDynamicSharedMemorySize,
                         ATT_SMEM_BYTES);

    // fused QKV projection: one launch, grid.z selects the weight matrix
    gemm_tf32<<<dim3(MROWS / 128, EMBED / 128, 3), 256, GEMM_SMEM_BYTES>>>(
        x, Wq, Wk, Wv, bq, bk, bv, nullptr, 1);

    attn_kernel<<<dim3(SEQ / 128, BATCH * HEADS), 256, ATT_SMEM_BYTES>>>();

    // output projection
    gemm_tf32<<<dim3(MROWS / 128, EMBED / 128, 1), 256, GEMM_SMEM_BYTES>>>(
        nullptr, Wo, Wo, Wo, bo, bo, bo, out, 0);
}

// round 5
// speedup vs baseline: 2.9624x; 1.9879x over previous
#include <cuda_runtime.h>
#include <cuda_fp16.h>
#include <stdint.h>

#define EMBED 1024
#define HEADS 16
#define HDIM  64
#define BATCH 2
#define SEQ   2048
#define MROWS (BATCH*SEQ)   // 4096

// ---------------- device scratch (alloc-free rule: __device__ globals) ------
__device__ __half g_Q[(size_t)BATCH*HEADS*SEQ*HDIM];   // [B,H,S,Dh]
__device__ __half g_K[(size_t)BATCH*HEADS*SEQ*HDIM];
__device__ __half g_V[(size_t)BATCH*HEADS*SEQ*HDIM];
__device__ __half g_A[(size_t)MROWS*EMBED];            // attention out, [B,S,E]
__device__ __half g_WT[(size_t)4*EMBED*EMBED];         // W^T (half) for q,k,v,o
__device__ __half g_Xh[(size_t)MROWS*EMBED];           // x in half

// ---------------- helpers ----------------------------------------------------
__device__ __forceinline__ float ex2f(float x) {
    float y;
    asm("ex2.approx.ftz.f32 %0, %1;" : "=f"(y) : "f"(x));
    return y;
}

__device__ __forceinline__ unsigned packh2(float lo, float hi) {
    __half2 h = __floats2half2_rn(lo, hi);
    return *(unsigned*)&h;
}

__device__ __forceinline__ void mma16(float* c, const unsigned* a, const unsigned* b) {
    asm volatile(
        "mma.sync.aligned.m16n8k16.row.col.f32.f16.f16.f32 "
        "{%0,%1,%2,%3}, {%4,%5,%6,%7}, {%8,%9}, {%0,%1,%2,%3};\n"
        : "+f"(c[0]), "+f"(c[1]), "+f"(c[2]), "+f"(c[3])
        : "r"(a[0]), "r"(a[1]), "r"(a[2]), "r"(a[3]), "r"(b[0]), "r"(b[1]));
}

__device__ __forceinline__ void cpa16(void* dst, const void* src) {
    unsigned d = (unsigned)__cvta_generic_to_shared(dst);
    asm volatile("cp.async.cg.shared.global [%0], [%1], 16;\n" :: "r"(d), "l"(src));
}

__device__ __forceinline__ void ldsm_t4(unsigned* r, const void* p) {
    unsigned a = (unsigned)__cvta_generic_to_shared(p);
    asm volatile("ldmatrix.sync.aligned.m8n8.x4.trans.shared.b16 {%0,%1,%2,%3}, [%4];"
                 : "=r"(r[0]), "=r"(r[1]), "=r"(r[2]), "=r"(r[3]) : "r"(a));
}

// ---------------- input conversions -----------------------------------------
__global__ void convert_x(const float* __restrict__ x) {
    int i = blockIdx.x * 256 + threadIdx.x;          // float4 index
    float4 v = ((const float4*)x)[i];
    uint2 u;
    u.x = packh2(v.x, v.y);
    u.y = packh2(v.z, v.w);
    ((uint2*)g_Xh)[i] = u;
}

// g_WT[z][n][k] = half(W_z[k][n])
__global__ void transpose_w(const float* __restrict__ W0, const float* __restrict__ W1,
                            const float* __restrict__ W2, const float* __restrict__ W3)
{
    __shared__ float t[32][33];
    int z = blockIdx.z;
    const float* W = (z == 0) ? W0 : (z == 1) ? W1 : (z == 2) ? W2 : W3;
    __half* T = g_WT + (size_t)z * EMBED * EMBED;
    int x0 = blockIdx.x * 32, y0 = blockIdx.y * 32;
    int tx = threadIdx.x, ty = threadIdx.y;
#pragma unroll
    for (int j = 0; j < 4; j++)
        t[ty + 8 * j][tx] = W[(size_t)(y0 + ty + 8 * j) * EMBED + x0 + tx];
    __syncthreads();
#pragma unroll
    for (int j = 0; j < 4; j++)
        T[(size_t)(x0 + ty + 8 * j) * EMBED + y0 + tx] = __float2half_rn(t[tx][ty + 8 * j]);
}

// ---------------- fp16 GEMM: C = A[4096x1024] * W + bias --------------------
// split=1: A=g_Xh, z selects W^T/bias, C = g_Q/g_K/g_V (half, split-head)
// split=0: A=g_A,  C=d_out (float, row-major)
#define AL 40                               // halfs per 32-half tile row (pad 8)
#define G_STG (128*AL*2*2)                  // A+B tile bytes per stage: 20480
#define GEMM_SMEM (1024 + 2*G_STG)          // 41984

__global__ __launch_bounds__(256, 2)
void gemm_h(const float* __restrict__ B0, const float* __restrict__ B1,
            const float* __restrict__ B2,
            float* __restrict__ Cext, int split)
{
    extern __shared__ char smb[];
    float* bias_s = (float*)(smb + 512);

    int z = blockIdx.z;
    const __half* A  = split ? g_Xh : g_A;
    const __half* WT = g_WT + (size_t)(split ? z : 3) * EMBED * EMBED;
    const float* bias = split ? ((z == 0) ? B0 : (z == 1) ? B1 : B2) : B0;

    int m0 = blockIdx.x * 128;
    int n0 = blockIdx.y * 128;
    int tid = threadIdx.x;
    int wid = tid >> 5, lane = tid & 31;
    int gid = lane >> 2, tig = lane & 3;
    int wrow = wid >> 2, wcol = wid & 3;    // 2x4 warps, each 64x32

    if (tid < 128) bias_s[tid] = bias[n0 + tid];

    float c[4][4][4];
#pragma unroll
    for (int i = 0; i < 4; i++)
#pragma unroll
        for (int j = 0; j < 4; j++)
#pragma unroll
            for (int k = 0; k < 4; k++) c[i][j][k] = 0.f;

    auto issue = [&](int s, int kt) {
        __half* As = (__half*)(smb + 1024 + s * G_STG);
        __half* Bs = As + 128 * AL;
#pragma unroll
        for (int i = 0; i < 2; i++) {
            int idx = tid + i * 256;
            int r = idx >> 2, c4 = idx & 3;
            cpa16(As + r * AL + c4 * 8, A + (size_t)(m0 + r) * EMBED + kt + c4 * 8);
        }
#pragma unroll
        for (int i = 0; i < 2; i++) {
            int idx = tid + i * 256;
            int r = idx >> 2, c4 = idx & 3;
            cpa16(Bs + r * AL + c4 * 8, WT + (size_t)(n0 + r) * EMBED + kt + c4 * 8);
        }
        asm volatile("cp.async.commit_group;");
    };

    issue(0, 0);

    for (int t = 0; t < EMBED / 32; t++) {
        int s = t & 1;
        if (t + 1 < EMBED / 32) {
            issue(s ^ 1, (t + 1) * 32);
            asm volatile("cp.async.wait_group 1;");
        } else {
            asm volatile("cp.async.wait_group 0;");
        }
        __syncthreads();

        const __half* As = (const __half*)(smb + 1024 + s * G_STG);
        const __half* Bs = As + 128 * AL;

#pragma unroll
        for (int kk = 0; kk < 32; kk += 16) {
            unsigned af[4][4], bf[4][2];
#pragma unroll
            for (int mf = 0; mf < 4; mf++) {
                const __half* p = As + (wrow * 64 + mf * 16 + gid) * AL + kk + tig * 2;
                af[mf][0] = *(const unsigned*)(p);
                af[mf][1] = *(const unsigned*)(p + 8 * AL);
                af[mf][2] = *(const unsigned*)(p + 8);
                af[mf][3] = *(const unsigned*)(p + 8 * AL + 8);
            }
#pragma unroll
            for (int nf = 0; nf < 4; nf++) {
                const __half* p = Bs + (wcol * 32 + nf * 8 + gid) * AL + kk + tig * 2;
                bf[nf][0] = *(const unsigned*)(p);
                bf[nf][1] = *(const unsigned*)(p + 8);
            }
#pragma unroll
            for (int mf = 0; mf < 4; mf++)
#pragma unroll
                for (int nf = 0; nf < 4; nf++)
                    mma16(c[mf][nf], af[mf], bf[nf]);
        }
        __syncthreads();
    }

    if (split) {
        // half output, restage through smem for coalesced 16B stores
        __half* ep = (__half*)(smb + 1024);
        __half* C = (z == 0) ? g_Q : (z == 1) ? g_K : g_V;
#pragma unroll
        for (int mf = 0; mf < 4; mf++)
#pragma unroll
            for (int nf = 0; nf < 4; nf++) {
                int r = wrow * 64 + mf * 16 + gid;
                int n = wcol * 32 + nf * 8 + tig * 2;
                float b0v = bias_s[n], b1v = bias_s[n + 1];
                *(unsigned*)(ep + r * 136 + n) =
                    packh2(c[mf][nf][0] + b0v, c[mf][nf][1] + b1v);
                *(unsigned*)(ep + (r + 8) * 136 + n) =
                    packh2(c[mf][nf][2] + b0v, c[mf][nf][3] + b1v);
            }
        __syncthreads();
#pragma unroll
        for (int i = 0; i < 8; i++) {
            int idx = tid + i * 256;
            int rr = idx >> 4, c8 = idx & 15;
            uint4 v = *(const uint4*)(ep + rr * 136 + c8 * 8);
            int r_g = m0 + rr;
            int n = n0 + c8 * 8;
            int b = r_g >> 11, s2 = r_g & 2047;
            int h = n >> 6, d = n & 63;
            size_t oidx = (((size_t)(b * HEADS + h)) * SEQ + s2) * HDIM + d;
            *(uint4*)(C + oidx) = v;
        }
    } else {
        // float output, direct float2 stores
#pragma unroll
        for (int mf = 0; mf < 4; mf++)
#pragma unroll
            for (int nf = 0; nf < 4; nf++) {
                int rbase = m0 + wrow * 64 + mf * 16 + gid;
                int n = n0 + wcol * 32 + nf * 8 + tig * 2;
                float b0v = bias_s[n - n0], b1v = bias_s[n - n0 + 1];
                *(float2*)(Cext + (size_t)rbase * EMBED + n) =
                    make_float2(c[mf][nf][0] + b0v, c[mf][nf][1] + b1v);
                *(float2*)(Cext + (size_t)(rbase + 8) * EMBED + n) =
                    make_float2(c[mf][nf][2] + b0v, c[mf][nf][3] + b1v);
            }
    }
}

// ---------------- fused flash attention (fp16 mma, register softmax) --------
// grid (16 qb, 32 bh), 256 threads. Warp w owns query rows [16w,16w+16).
#define KL 72     // halfs per 64-half row (pad 8)
#define ATT_SMEM (4*128*KL*2)   // K0,K1,V0,V1 = 73728 bytes

__global__ __launch_bounds__(256, 1)
void attn_kernel()
{
    extern __shared__ char smb[];
    __half* K0 = (__half*)smb;
    __half* K1 = K0 + 128 * KL;
    __half* V0 = K1 + 128 * KL;
    __half* V1 = V0 + 128 * KL;

    int qb = blockIdx.x;
    int bh = blockIdx.y;
    int tid = threadIdx.x;
    int wid = tid >> 5, lane = tid & 31;
    int gid = lane >> 2, tig = lane & 3;

    const __half* Qg = g_Q + (size_t)bh * SEQ * HDIM + (size_t)qb * 128 * HDIM;
    const __half* Kg = g_K + (size_t)bh * SEQ * HDIM;
    const __half* Vg = g_V + (size_t)bh * SEQ * HDIM;

    // ---- stage Q through K0, extract per-warp Q fragments (4 k16 chunks) ----
#pragma unroll
    for (int i = 0; i < 4; i++) {
        int idx = tid + i * 256;
        int r = idx >> 3, c8 = idx & 7;
        *(uint4*)(K0 + r * KL + c8 * 8) = *(const uint4*)(Qg + (size_t)r * HDIM + c8 * 8);
    }
    __syncthreads();
    unsigned qf[4][4];
    {
        const __half* p0 = K0 + (wid * 16 + gid) * KL;
#pragma unroll
        for (int kc = 0; kc < 4; kc++) {
            const __half* p = p0 + kc * 16 + tig * 2;
            qf[kc][0] = *(const unsigned*)(p);
            qf[kc][1] = *(const unsigned*)(p + 8 * KL);
            qf[kc][2] = *(const unsigned*)(p + 8);
            qf[kc][3] = *(const unsigned*)(p + 8 * KL + 8);
        }
    }
    __syncthreads();

    float o[8][4];
#pragma unroll
    for (int i = 0; i < 8; i++)
#pragma unroll
        for (int j = 0; j < 4; j++) o[i][j] = 0.f;

    float m0 = -1e30f, m1 = -1e30f, l0 = 0.f, l1 = 0.f;
    const float CC = 0.125f * 1.44269504f;   // (1/sqrt(64)) * log2(e)

    auto issueKV = [&](int j, int s) {
        __half* Kd = s ? K1 : K0;
        __half* Vd = s ? V1 : V0;
        const __half* Ks = Kg + (size_t)j * 128 * HDIM;
        const __half* Vs = Vg + (size_t)j * 128 * HDIM;
#pragma unroll
        for (int i = 0; i < 4; i++) {
            int idx = tid + i * 256;
            int r = idx >> 3, c8 = idx & 7;
            cpa16(Kd + r * KL + c8 * 8, Ks + (size_t)r * HDIM + c8 * 8);
        }
#pragma unroll
        for (int i = 0; i < 4; i++) {
            int idx = tid + i * 256;
            int r = idx >> 3, c8 = idx & 7;
            cpa16(Vd + r * KL + c8 * 8, Vs + (size_t)r * HDIM + c8 * 8);
        }
        asm volatile("cp.async.commit_group;");
    };

    issueKV(0, 0);

    for (int j = 0; j < SEQ / 128; j++) {
        int s = j & 1;
        if (j + 1 < SEQ / 128) {
            issueKV(j + 1, s ^ 1);
            asm volatile("cp.async.wait_group 1;");
        } else {
            asm volatile("cp.async.wait_group 0;");
        }
        __syncthreads();

        const __half* Kb = s ? K1 : K0;
        const __half* Vb = s ? V1 : V0;

        // ---- S = Q K^T (warp: 16 rows x 128 cols, registers) ----
        float sv[16][4];
#pragma unroll
        for (int nf = 0; nf < 16; nf++)
#pragma unroll
            for (int k = 0; k < 4; k++) sv[nf][k] = 0.f;

#pragma unroll
        for (int kc = 0; kc < 4; kc++) {
#pragma unroll
            for (int nf = 0; nf < 16; nf++) {
                const __half* pb = Kb + (nf * 8 + gid) * KL + kc * 16 + tig * 2;
                unsigned bf[2] = { *(const unsigned*)(pb), *(const unsigned*)(pb + 8) };
                mma16(sv[nf], qf[kc], bf);
            }
        }

        // ---- online softmax in registers ----
        float mx0 = -1e30f, mx1 = -1e30f;
#pragma unroll
        for (int nf = 0; nf < 16; nf++) {
            mx0 = fmaxf(mx0, fmaxf(sv[nf][0], sv[nf][1]));
            mx1 = fmaxf(mx1, fmaxf(sv[nf][2], sv[nf][3]));
        }
        mx0 = fmaxf(mx0, __shfl_xor_sync(0xffffffffu, mx0, 1));
        mx0 = fmaxf(mx0, __shfl_xor_sync(0xffffffffu, mx0, 2));
        mx1 = fmaxf(mx1, __shfl_xor_sync(0xffffffffu, mx1, 1));
        mx1 = fmaxf(mx1, __shfl_xor_sync(0xffffffffu, mx1, 2));

        float mn0 = fmaxf(m0, mx0 * CC);
        float mn1 = fmaxf(m1, mx1 * CC);
        float al0 = ex2f(m0 - mn0);
        float al1 = ex2f(m1 - mn1);

        float s0 = 0.f, s1 = 0.f;
#pragma unroll
        for (int nf = 0; nf < 16; nf++) {
            float p;
            p = ex2f(fmaf(sv[nf][0], CC, -mn0)); sv[nf][0] = p; s0 += p;
            p = ex2f(fmaf(sv[nf][1], CC, -mn0)); sv[nf][1] = p; s0 += p;
            p = ex2f(fmaf(sv[nf][2], CC, -mn1)); sv[nf][2] = p; s1 += p;
            p = ex2f(fmaf(sv[nf][3], CC, -mn1)); sv[nf][3] = p; s1 += p;
        }
        s0 += __shfl_xor_sync(0xffffffffu, s0, 1);
        s0 += __shfl_xor_sync(0xffffffffu, s0, 2);
        s1 += __shfl_xor_sync(0xffffffffu, s1, 1);
        s1 += __shfl_xor_sync(0xffffffffu, s1, 2);

        l0 = l0 * al0 + s0;
        l1 = l1 * al1 + s1;
        m0 = mn0; m1 = mn1;

#pragma unroll
        for (int vf = 0; vf < 8; vf++) {
            o[vf][0] *= al0; o[vf][1] *= al0;
            o[vf][2] *= al1; o[vf][3] *= al1;
        }

        // ---- O += P V : P packs directly to A-frags; V via ldmatrix.trans ----
#pragma unroll
        for (int kc = 0; kc < 8; kc++) {
            unsigned a[4];
            a[0] = packh2(sv[2 * kc][0],     sv[2 * kc][1]);
            a[1] = packh2(sv[2 * kc][2],     sv[2 * kc][3]);
            a[2] = packh2(sv[2 * kc + 1][0], sv[2 * kc + 1][1]);
            a[3] = packh2(sv[2 * kc + 1][2], sv[2 * kc + 1][3]);
#pragma unroll
            for (int vf2 = 0; vf2 < 4; vf2++) {
                unsigned r[4];
                const __half* pv = Vb + (kc * 16 + (lane & 15)) * KL
                                      + vf2 * 16 + (lane >> 4) * 8;
                ldsm_t4(r, pv);
                mma16(o[2 * vf2],     a, r);
                mma16(o[2 * vf2 + 1], a, r + 2);
            }
        }
        __syncthreads();
    }

    // ---- epilogue: O/l -> half, write g_A in [B,S,E] layout ----
    {
        int b = bh >> 4, h = bh & 15;
        float li0 = 1.f / l0;
        float li1 = 1.f / l1;
        size_t row = (size_t)(b * SEQ + qb * 128 + wid * 16 + gid);
#pragma unroll
        for (int vf = 0; vf < 8; vf++) {
            int d = vf * 8 + tig * 2;
            size_t base = row * EMBED + (size_t)h * HDIM + d;
            *(unsigned*)(g_A + base) = packh2(o[vf][0] * li0, o[vf][1] * li0);
            *(unsigned*)(g_A + base + 8 * EMBED) = packh2(o[vf][2] * li1, o[vf][3] * li1);
        }
    }
}

// ---------------- launch ----------------------------------------------------
extern "C" void kernel_launch(void* const* d_in, const int* in_sizes, int n_in,
                              void* d_out, int out_size)
{
    const float* x  = (const float*)d_in[0];
    const float* Wq = (const float*)d_in[1];
    const float* bq = (const float*)d_in[2];
    const float* Wk = (const float*)d_in[3];
    const float* bk = (const float*)d_in[4];
    const float* Wv = (const float*)d_in[5];
    const float* bv = (const float*)d_in[6];
    const float* Wo = (const float*)d_in[7];
    const float* bo = (const float*)d_in[8];
    float* out = (float*)d_out;

    cudaFuncSetAttribute(gemm_h, cudaFuncAttributeMaxDynamicSharedMemorySize, GEMM_SMEM);
    cudaFuncSetAttribute(attn_kernel, cudaFuncAttributeMaxDynamicSharedMemorySize, ATT_SMEM);

    convert_x<<<MROWS * EMBED / 4 / 256, 256>>>(x);
    transpose_w<<<dim3(EMBED / 32, EMBED / 32, 4), dim3(32, 8)>>>(Wq, Wk, Wv, Wo);

    gemm_h<<<dim3(MROWS / 128, EMBED / 128, 3), 256, GEMM_SMEM>>>(bq, bk, bv, nullptr, 1);

    attn_kernel<<<dim3(SEQ / 128, BATCH * HEADS), 256, ATT_SMEM>>>();

    gemm_h<<<dim3(MROWS / 128, EMBED / 128, 1), 256, GEMM_SMEM>>>(bo, bo, bo, out, 0);
}

// round 6
// speedup vs baseline: 3.3255x; 1.1226x over previous
#include <cuda_runtime.h>
#include <cuda_fp16.h>
#include <stdint.h>

#define EMBED 1024
#define HEADS 16
#define HDIM  64
#define BATCH 2
#define SEQ   2048
#define MROWS (BATCH*SEQ)   // 4096

// ---------------- device scratch (alloc-free rule: __device__ globals) ------
__device__ __half g_Q[(size_t)BATCH*HEADS*SEQ*HDIM];   // [B,H,S,Dh]
__device__ __half g_K[(size_t)BATCH*HEADS*SEQ*HDIM];
__device__ __half g_V[(size_t)BATCH*HEADS*SEQ*HDIM];
__device__ __half g_A[(size_t)MROWS*EMBED];            // attention out, [B,S,E]
__device__ __half g_WT[(size_t)4*EMBED*EMBED];         // W^T (half) for q,k,v,o
__device__ __half g_Xh[(size_t)MROWS*EMBED];           // x in half

// ---------------- helpers ----------------------------------------------------
__device__ __forceinline__ float ex2f(float x) {
    float y;
    asm("ex2.approx.ftz.f32 %0, %1;" : "=f"(y) : "f"(x));
    return y;
}

__device__ __forceinline__ unsigned packh2(float lo, float hi) {
    __half2 h = __floats2half2_rn(lo, hi);
    return *(unsigned*)&h;
}

__device__ __forceinline__ void mma16(float* c, const unsigned* a, const unsigned* b) {
    asm volatile(
        "mma.sync.aligned.m16n8k16.row.col.f32.f16.f16.f32 "
        "{%0,%1,%2,%3}, {%4,%5,%6,%7}, {%8,%9}, {%0,%1,%2,%3};\n"
        : "+f"(c[0]), "+f"(c[1]), "+f"(c[2]), "+f"(c[3])
        : "r"(a[0]), "r"(a[1]), "r"(a[2]), "r"(a[3]), "r"(b[0]), "r"(b[1]));
}

__device__ __forceinline__ void cpa16(void* dst, const void* src) {
    unsigned d = (unsigned)__cvta_generic_to_shared(dst);
    asm volatile("cp.async.cg.shared.global [%0], [%1], 16;\n" :: "r"(d), "l"(src));
}

__device__ __forceinline__ void ldsm4(unsigned* r, const void* p) {
    unsigned a = (unsigned)__cvta_generic_to_shared(p);
    asm volatile("ldmatrix.sync.aligned.m8n8.x4.shared.b16 {%0,%1,%2,%3}, [%4];"
                 : "=r"(r[0]), "=r"(r[1]), "=r"(r[2]), "=r"(r[3]) : "r"(a));
}

__device__ __forceinline__ void ldsm_t4(unsigned* r, const void* p) {
    unsigned a = (unsigned)__cvta_generic_to_shared(p);
    asm volatile("ldmatrix.sync.aligned.m8n8.x4.trans.shared.b16 {%0,%1,%2,%3}, [%4];"
                 : "=r"(r[0]), "=r"(r[1]), "=r"(r[2]), "=r"(r[3]) : "r"(a));
}

// ---------------- input conversions -----------------------------------------
__global__ void convert_x(const float* __restrict__ x) {
    int i = blockIdx.x * 256 + threadIdx.x;          // float4 index
    float4 v = ((const float4*)x)[i];
    uint2 u;
    u.x = packh2(v.x, v.y);
    u.y = packh2(v.z, v.w);
    ((uint2*)g_Xh)[i] = u;
}

// g_WT[z][n][k] = half(W_z[k][n])
__global__ void transpose_w(const float* __restrict__ W0, const float* __restrict__ W1,
                            const float* __restrict__ W2, const float* __restrict__ W3)
{
    __shared__ float t[32][33];
    int z = blockIdx.z;
    const float* W = (z == 0) ? W0 : (z == 1) ? W1 : (z == 2) ? W2 : W3;
    __half* T = g_WT + (size_t)z * EMBED * EMBED;
    int x0 = blockIdx.x * 32, y0 = blockIdx.y * 32;
    int tx = threadIdx.x, ty = threadIdx.y;
#pragma unroll
    for (int j = 0; j < 4; j++)
        t[ty + 8 * j][tx] = W[(size_t)(y0 + ty + 8 * j) * EMBED + x0 + tx];
    __syncthreads();
#pragma unroll
    for (int j = 0; j < 4; j++)
        T[(size_t)(x0 + ty + 8 * j) * EMBED + y0 + tx] = __float2half_rn(t[tx][ty + 8 * j]);
}

// ---------------- fp16 GEMM: C = A[4096x1024] * W + bias --------------------
// split=1: A=g_Xh, z selects W^T/bias, C = g_Q/g_K/g_V (half, split-head)
// split=0: A=g_A,  C=d_out (float, row-major)
// K-step 64, double-buffered; fragments via ldmatrix.x4 (stride 72h = odd 16B units)
#define AL2 72
#define TILE_B (128*AL2*2)                  // bytes per 128x64 tile: 18432
#define G_STG (2*TILE_B)                    // A+B per stage: 36864
#define GEMM_SMEM (1024 + 2*G_STG)          // 74752

__global__ __launch_bounds__(256, 2)
void gemm_h(const float* __restrict__ B0, const float* __restrict__ B1,
            const float* __restrict__ B2,
            float* __restrict__ Cext, int split)
{
    extern __shared__ char smb[];
    float* bias_s = (float*)(smb + 512);

    int z = blockIdx.z;
    const __half* A  = split ? g_Xh : g_A;
    const __half* WT = g_WT + (size_t)(split ? z : 3) * EMBED * EMBED;
    const float* bias = split ? ((z == 0) ? B0 : (z == 1) ? B1 : B2) : B0;

    int m0 = blockIdx.x * 128;
    int n0 = blockIdx.y * 128;
    int tid = threadIdx.x;
    int wid = tid >> 5, lane = tid & 31;
    int gid = lane >> 2, tig = lane & 3;
    int wrow = wid >> 2, wcol = wid & 3;    // 2x4 warps, each 64x32

    // ldmatrix lane->element offsets
    int lm_off  = lane & 7;
    int lm_b01  = (lane >> 3) & 1;   // tile bit 0
    int lm_b23  = (lane >> 4) & 1;   // tile bit 1

    if (tid < 128) bias_s[tid] = bias[n0 + tid];

    float c[4][4][4];
#pragma unroll
    for (int i = 0; i < 4; i++)
#pragma unroll
        for (int j = 0; j < 4; j++)
#pragma unroll
            for (int k = 0; k < 4; k++) c[i][j][k] = 0.f;

    auto issue = [&](int s, int kt) {
        __half* As = (__half*)(smb + 1024 + s * G_STG);
        __half* Bs = As + 128 * AL2;
#pragma unroll
        for (int i = 0; i < 4; i++) {
            int idx = tid + i * 256;
            int r = idx >> 3, c8 = idx & 7;
            cpa16(As + r * AL2 + c8 * 8, A + (size_t)(m0 + r) * EMBED + kt + c8 * 8);
        }
#pragma unroll
        for (int i = 0; i < 4; i++) {
            int idx = tid + i * 256;
            int r = idx >> 3, c8 = idx & 7;
            cpa16(Bs + r * AL2 + c8 * 8, WT + (size_t)(n0 + r) * EMBED + kt + c8 * 8);
        }
        asm volatile("cp.async.commit_group;");
    };

    issue(0, 0);

    for (int t = 0; t < EMBED / 64; t++) {
        int s = t & 1;
        if (t + 1 < EMBED / 64) {
            issue(s ^ 1, (t + 1) * 64);
            asm volatile("cp.async.wait_group 1;");
        } else {
            asm volatile("cp.async.wait_group 0;");
        }
        __syncthreads();

        const __half* As = (const __half*)(smb + 1024 + s * G_STG);
        const __half* Bs = As + 128 * AL2;

#pragma unroll
        for (int kk = 0; kk < 64; kk += 16) {
            unsigned af[4][4], bf[4][2];
#pragma unroll
            for (int mf = 0; mf < 4; mf++) {
                // A-frag: tiles (r0-7,k0-7)(r8-15,k0-7)(r0-7,k8-15)(r8-15,k8-15)
                const __half* p = As + (wrow * 64 + mf * 16 + lm_b01 * 8 + lm_off) * AL2
                                     + kk + lm_b23 * 8;
                ldsm4(af[mf], p);
            }
#pragma unroll
            for (int np = 0; np < 2; np++) {
                // B-frag pair: tiles (n0-7,k0-7)(n0-7,k8-15)(n8-15,k0-7)(n8-15,k8-15)
                const __half* p = Bs + (wcol * 32 + np * 16 + lm_b23 * 8 + lm_off) * AL2
                                     + kk + lm_b01 * 8;
                unsigned r[4];
                ldsm4(r, p);
                bf[np * 2][0] = r[0]; bf[np * 2][1] = r[1];
                bf[np * 2 + 1][0] = r[2]; bf[np * 2 + 1][1] = r[3];
            }
#pragma unroll
            for (int mf = 0; mf < 4; mf++)
#pragma unroll
                for (int nf = 0; nf < 4; nf++)
                    mma16(c[mf][nf], af[mf], bf[nf]);
        }
        __syncthreads();
    }

    if (split) {
        // half output, restage through smem for coalesced 16B stores
        __half* ep = (__half*)(smb + 1024);
        __half* C = (z == 0) ? g_Q : (z == 1) ? g_K : g_V;
#pragma unroll
        for (int mf = 0; mf < 4; mf++)
#pragma unroll
            for (int nf = 0; nf < 4; nf++) {
                int r = wrow * 64 + mf * 16 + gid;
                int n = wcol * 32 + nf * 8 + tig * 2;
                float b0v = bias_s[n], b1v = bias_s[n + 1];
                *(unsigned*)(ep + r * 136 + n) =
                    packh2(c[mf][nf][0] + b0v, c[mf][nf][1] + b1v);
                *(unsigned*)(ep + (r + 8) * 136 + n) =
                    packh2(c[mf][nf][2] + b0v, c[mf][nf][3] + b1v);
            }
        __syncthreads();
#pragma unroll
        for (int i = 0; i < 8; i++) {
            int idx = tid + i * 256;
            int rr = idx >> 4, c8 = idx & 15;
            uint4 v = *(const uint4*)(ep + rr * 136 + c8 * 8);
            int r_g = m0 + rr;
            int n = n0 + c8 * 8;
            int b = r_g >> 11, s2 = r_g & 2047;
            int h = n >> 6, d = n & 63;
            size_t oidx = (((size_t)(b * HEADS + h)) * SEQ + s2) * HDIM + d;
            *(uint4*)(C + oidx) = v;
        }
    } else {
        // float output, direct float2 stores
#pragma unroll
        for (int mf = 0; mf < 4; mf++)
#pragma unroll
            for (int nf = 0; nf < 4; nf++) {
                int rbase = m0 + wrow * 64 + mf * 16 + gid;
                int n = n0 + wcol * 32 + nf * 8 + tig * 2;
                float b0v = bias_s[n - n0], b1v = bias_s[n - n0 + 1];
                *(float2*)(Cext + (size_t)rbase * EMBED + n) =
                    make_float2(c[mf][nf][0] + b0v, c[mf][nf][1] + b1v);
                *(float2*)(Cext + (size_t)(rbase + 8) * EMBED + n) =
                    make_float2(c[mf][nf][2] + b0v, c[mf][nf][3] + b1v);
            }
    }
}

// ---------------- fused flash attention (fp16 mma, register softmax) --------
// grid (16 qb, 32 bh), 256 threads. Warp w owns query rows [16w,16w+16).
// K fragments via ldmatrix.x4 (non-trans), V via ldmatrix.x4.trans.
#define KL 72     // halfs per 64-half row (pad 8; odd 16B stride -> conflict-free)
#define ATT_SMEM (4*128*KL*2)   // K0,K1,V0,V1 = 73728 bytes

__global__ __launch_bounds__(256, 1)
void attn_kernel()
{
    extern __shared__ char smb[];
    __half* K0 = (__half*)smb;
    __half* K1 = K0 + 128 * KL;
    __half* V0 = K1 + 128 * KL;
    __half* V1 = V0 + 128 * KL;

    int qb = blockIdx.x;
    int bh = blockIdx.y;
    int tid = threadIdx.x;
    int wid = tid >> 5, lane = tid & 31;
    int gid = lane >> 2, tig = lane & 3;

    int lm_off = lane & 7;
    int lm_b01 = (lane >> 3) & 1;
    int lm_b23 = (lane >> 4) & 1;

    const __half* Qg = g_Q + (size_t)bh * SEQ * HDIM + (size_t)qb * 128 * HDIM;
    const __half* Kg = g_K + (size_t)bh * SEQ * HDIM;
    const __half* Vg = g_V + (size_t)bh * SEQ * HDIM;

    // ---- stage Q through K0, extract per-warp Q fragments via ldmatrix ----
#pragma unroll
    for (int i = 0; i < 4; i++) {
        int idx = tid + i * 256;
        int r = idx >> 3, c8 = idx & 7;
        *(uint4*)(K0 + r * KL + c8 * 8) = *(const uint4*)(Qg + (size_t)r * HDIM + c8 * 8);
    }
    __syncthreads();
    unsigned qf[4][4];
#pragma unroll
    for (int kc = 0; kc < 4; kc++) {
        const __half* p = K0 + (wid * 16 + lm_b01 * 8 + lm_off) * KL
                             + kc * 16 + lm_b23 * 8;
        ldsm4(qf[kc], p);
    }
    __syncthreads();

    float o[8][4];
#pragma unroll
    for (int i = 0; i < 8; i++)
#pragma unroll
        for (int j = 0; j < 4; j++) o[i][j] = 0.f;

    float m0 = -1e30f, m1 = -1e30f, l0 = 0.f, l1 = 0.f;
    const float CC = 0.125f * 1.44269504f;   // (1/sqrt(64)) * log2(e)

    auto issueKV = [&](int j, int s) {
        __half* Kd = s ? K1 : K0;
        __half* Vd = s ? V1 : V0;
        const __half* Ks = Kg + (size_t)j * 128 * HDIM;
        const __half* Vs = Vg + (size_t)j * 128 * HDIM;
#pragma unroll
        for (int i = 0; i < 4; i++) {
            int idx = tid + i * 256;
            int r = idx >> 3, c8 = idx & 7;
            cpa16(Kd + r * KL + c8 * 8, Ks + (size_t)r * HDIM + c8 * 8);
        }
#pragma unroll
        for (int i = 0; i < 4; i++) {
            int idx = tid + i * 256;
            int r = idx >> 3, c8 = idx & 7;
            cpa16(Vd + r * KL + c8 * 8, Vs + (size_t)r * HDIM + c8 * 8);
        }
        asm volatile("cp.async.commit_group;");
    };

    issueKV(0, 0);

    for (int j = 0; j < SEQ / 128; j++) {
        int s = j & 1;
        if (j + 1 < SEQ / 128) {
            issueKV(j + 1, s ^ 1);
            asm volatile("cp.async.wait_group 1;");
        } else {
            asm volatile("cp.async.wait_group 0;");
        }
        __syncthreads();

        const __half* Kb = s ? K1 : K0;
        const __half* Vb = s ? V1 : V0;

        // ---- S = Q K^T (warp: 16 rows x 128 cols, registers) ----
        float sv[16][4];
#pragma unroll
        for (int nf = 0; nf < 16; nf++)
#pragma unroll
            for (int k = 0; k < 4; k++) sv[nf][k] = 0.f;

#pragma unroll
        for (int kc = 0; kc < 4; kc++) {
#pragma unroll
            for (int np = 0; np < 8; np++) {
                // B-frag pair via ldmatrix: tiles (n0-7,kLo)(n0-7,kHi)(n8-15,kLo)(n8-15,kHi)
                const __half* p = Kb + (np * 16 + lm_b23 * 8 + lm_off) * KL
                                     + kc * 16 + lm_b01 * 8;
                unsigned r[4];
                ldsm4(r, p);
                mma16(sv[np * 2],     qf[kc], r);
                mma16(sv[np * 2 + 1], qf[kc], r + 2);
            }
        }

        // ---- online softmax in registers ----
        float mx0 = -1e30f, mx1 = -1e30f;
#pragma unroll
        for (int nf = 0; nf < 16; nf++) {
            mx0 = fmaxf(mx0, fmaxf(sv[nf][0], sv[nf][1]));
            mx1 = fmaxf(mx1, fmaxf(sv[nf][2], sv[nf][3]));
        }
        mx0 = fmaxf(mx0, __shfl_xor_sync(0xffffffffu, mx0, 1));
        mx0 = fmaxf(mx0, __shfl_xor_sync(0xffffffffu, mx0, 2));
        mx1 = fmaxf(mx1, __shfl_xor_sync(0xffffffffu, mx1, 1));
        mx1 = fmaxf(mx1, __shfl_xor_sync(0xffffffffu, mx1, 2));

        float mn0 = fmaxf(m0, mx0 * CC);
        float mn1 = fmaxf(m1, mx1 * CC);
        float al0 = ex2f(m0 - mn0);
        float al1 = ex2f(m1 - mn1);

        float s0 = 0.f, s1 = 0.f;
#pragma unroll
        for (int nf = 0; nf < 16; nf++) {
            float p;
            p = ex2f(fmaf(sv[nf][0], CC, -mn0)); sv[nf][0] = p; s0 += p;
            p = ex2f(fmaf(sv[nf][1], CC, -mn0)); sv[nf][1] = p; s0 += p;
            p = ex2f(fmaf(sv[nf][2], CC, -mn1)); sv[nf][2] = p; s1 += p;
            p = ex2f(fmaf(sv[nf][3], CC, -mn1)); sv[nf][3] = p; s1 += p;
        }
        s0 += __shfl_xor_sync(0xffffffffu, s0, 1);
        s0 += __shfl_xor_sync(0xffffffffu, s0, 2);
        s1 += __shfl_xor_sync(0xffffffffu, s1, 1);
        s1 += __shfl_xor_sync(0xffffffffu, s1, 2);

        l0 = l0 * al0 + s0;
        l1 = l1 * al1 + s1;
        m0 = mn0; m1 = mn1;

#pragma unroll
        for (int vf = 0; vf < 8; vf++) {
            o[vf][0] *= al0; o[vf][1] *= al0;
            o[vf][2] *= al1; o[vf][3] *= al1;
        }

        // ---- O += P V : P packs directly to A-frags; V via ldmatrix.trans ----
#pragma unroll
        for (int kc = 0; kc < 8; kc++) {
            unsigned a[4];
            a[0] = packh2(sv[2 * kc][0],     sv[2 * kc][1]);
            a[1] = packh2(sv[2 * kc][2],     sv[2 * kc][3]);
            a[2] = packh2(sv[2 * kc + 1][0], sv[2 * kc + 1][1]);
            a[3] = packh2(sv[2 * kc + 1][2], sv[2 * kc + 1][3]);
#pragma unroll
            for (int vf2 = 0; vf2 < 4; vf2++) {
                unsigned r[4];
                const __half* pv = Vb + (kc * 16 + (lane & 15)) * KL
                                      + vf2 * 16 + (lane >> 4) * 8;
                ldsm_t4(r, pv);
                mma16(o[2 * vf2],     a, r);
                mma16(o[2 * vf2 + 1], a, r + 2);
            }
        }
        __syncthreads();
    }

    // ---- epilogue: O/l -> half, write g_A in [B,S,E] layout ----
    {
        int b = bh >> 4, h = bh & 15;
        float li0 = 1.f / l0;
        float li1 = 1.f / l1;
        size_t row = (size_t)(b * SEQ + qb * 128 + wid * 16 + gid);
#pragma unroll
        for (int vf = 0; vf < 8; vf++) {
            int d = vf * 8 + tig * 2;
            size_t base = row * EMBED + (size_t)h * HDIM + d;
            *(unsigned*)(g_A + base) = packh2(o[vf][0] * li0, o[vf][1] * li0);
            *(unsigned*)(g_A + base + 8 * EMBED) = packh2(o[vf][2] * li1, o[vf][3] * li1);
        }
    }
}

// ---------------- launch ----------------------------------------------------
extern "C" void kernel_launch(void* const* d_in, const int* in_sizes, int n_in,
                              void* d_out, int out_size)
{
    const float* x  = (const float*)d_in[0];
    const float* Wq = (const float*)d_in[1];
    const float* bq = (const float*)d_in[2];
    const float* Wk = (const float*)d_in[3];
    const float* bk = (const float*)d_in[4];
    const float* Wv = (const float*)d_in[5];
    const float* bv = (const float*)d_in[6];
    const float* Wo = (const float*)d_in[7];
    const float* bo = (const float*)d_in[8];
    float* out = (float*)d_out;

    cudaFuncSetAttribute(gemm_h, cudaFuncAttributeMaxDynamicSharedMemorySize, GEMM_SMEM);
    cudaFuncSetAttribute(attn_kernel, cudaFuncAttributeMaxDynamicSharedMemorySize, ATT_SMEM);

    convert_x<<<MROWS * EMBED / 4 / 256, 256>>>(x);
    transpose_w<<<dim3(EMBED / 32, EMBED / 32, 4), dim3(32, 8)>>>(Wq, Wk, Wv, Wo);

    gemm_h<<<dim3(MROWS / 128, EMBED / 128, 3), 256, GEMM_SMEM>>>(bq, bk, bv, nullptr, 1);

    attn_kernel<<<dim3(SEQ / 128, BATCH * HEADS), 256, ATT_SMEM>>>();

    gemm_h<<<dim3(MROWS / 128, EMBED / 128, 1), 256, GEMM_SMEM>>>(bo, bo, bo, out, 0);
}